// round 1
// baseline (speedup 1.0000x reference)
#include <cuda_runtime.h>
#include <math.h>

#define BATCH 4
#define SEQ 2048
#define IND 1024
#define H 4          // kv heads
#define D 64
#define HD 256       // H*D
#define NTOK (BATCH*SEQ)  // 8192

// ---------------- scratch (no allocs allowed) ----------------
__device__ __align__(16) float g_Wqeff[IND*HD];     // 1 MB
__device__ __align__(16) float g_q[NTOK*HD];        // 8 MB  (roped, pre-scaled by 1/8)
__device__ __align__(16) float g_k[NTOK*HD];        // 8 MB  (roped)
__device__ __align__(16) float g_v[NTOK*HD];        // 8 MB
__device__ __align__(16) float g_ao[NTOK*HD];       // 8 MB  (attention output, [tok, h*64+d])

// ---------------- Wq group-sum: Wq [1024,16,64] -> Wq_eff [1024, 4*64] ----------------
__global__ void wqeff_kernel(const float* __restrict__ Wq) {
    int idx = blockIdx.x * blockDim.x + threadIdx.x;
    if (idx >= IND * HD) return;
    int i  = idx / HD;
    int hd = idx % HD;
    int h = hd / D, d = hd % D;
    const float* base = Wq + (size_t)i * 1024 + (h * 4) * 64 + d;
    g_Wqeff[idx] = base[0] + base[64] + base[128] + base[192];
}

// ---------------- generic fp32 tiled GEMM: C[M,N] = A[M,K] @ B[K,N], all row-major ----------------
// BM=BN=64, BK=16, 256 threads, 4x4 per thread
__global__ void gemm_rrr(const float* __restrict__ A, const float* __restrict__ Bm,
                         float* __restrict__ C, int M, int N, int K) {
    __shared__ __align__(16) float As[16][68];   // transposed: As[k][m]
    __shared__ __align__(16) float Bs[16][64];
    const int tid = threadIdx.x;
    const int tx = tid & 15, ty = tid >> 4;
    const int m0 = blockIdx.y * 64, n0 = blockIdx.x * 64;

    float acc[4][4] = {};

    for (int k0 = 0; k0 < K; k0 += 16) {
        // A tile 64x16: 256 float4 loads (1 per thread), store transposed
        {
            int row = tid >> 2;             // 0..63
            int cg  = (tid & 3) << 2;       // 0,4,8,12
            float4 v = *(const float4*)(A + (size_t)(m0 + row) * K + k0 + cg);
            As[cg + 0][row] = v.x;
            As[cg + 1][row] = v.y;
            As[cg + 2][row] = v.z;
            As[cg + 3][row] = v.w;
            // B tile 16x64
            int brow = tid >> 4;            // 0..15
            int bcg  = (tid & 15) << 2;
            *(float4*)&Bs[brow][bcg] = *(const float4*)(Bm + (size_t)(k0 + brow) * N + n0 + bcg);
        }
        __syncthreads();
#pragma unroll
        for (int k = 0; k < 16; k++) {
            float4 a4 = *(const float4*)&As[k][4 * ty];
            float4 b4 = *(const float4*)&Bs[k][4 * tx];
            float av[4] = {a4.x, a4.y, a4.z, a4.w};
            float bv[4] = {b4.x, b4.y, b4.z, b4.w};
#pragma unroll
            for (int i = 0; i < 4; i++)
#pragma unroll
                for (int j = 0; j < 4; j++)
                    acc[i][j] += av[i] * bv[j];
        }
        __syncthreads();
    }
#pragma unroll
    for (int i = 0; i < 4; i++) {
        float4 o = {acc[i][0], acc[i][1], acc[i][2], acc[i][3]};
        *(float4*)(C + (size_t)(m0 + 4 * ty + i) * N + n0 + 4 * tx) = o;
    }
}

// ---------------- N-D RoPE (in place), coords int32 [ntok, 2], x [ntok, H, D] ----------------
// d=64, a=2 => 32 pairs; pair p: axis = p>>4, f = p&15, ang = coord[axis] * 10000^(-f/16)
__global__ void rope_kernel(float* __restrict__ x, const int* __restrict__ coords, float scale) {
    int idx = blockIdx.x * blockDim.x + threadIdx.x;
    if (idx >= NTOK * H * 32) return;
    int p   = idx & 31;
    int th  = idx >> 5;        // token*H + h
    int tok = th >> 2;
    int axis = p >> 4;
    int f    = p & 15;
    // fp64 angle computation: bounds our error at jax's own fp32 rounding error
    double inv = exp(-(double)f * (9.210340371976184 / 16.0)); // ln(10000)=9.2103...
    double ang = (double)coords[tok * 2 + axis] * inv;
    double sd, cd;
    sincos(ang, &sd, &cd);
    float sn = (float)sd, cs = (float)cd;
    float* px = x + (size_t)th * D + 2 * p;
    float x1 = px[0], x2 = px[1];
    px[0] = (x1 * cs - x2 * sn) * scale;
    px[1] = (x1 * sn + x2 * cs) * scale;
}

// ---------------- flash attention, fp32, BQ=BKV=64, 256 threads ----------------
// grid: (SEQ/64, H, BATCH). Q pre-scaled by 1/8. No mask (full attention).
#define STR 68
__device__ __forceinline__ float f4c(const float4& v, int j) {
    return j == 0 ? v.x : (j == 1 ? v.y : (j == 2 ? v.z : v.w));
}

__global__ void attn_kernel() {
    extern __shared__ __align__(16) float sm[];
    float* Qs = sm;                 // [64][STR]  q-row major
    float* Kt = Qs + 64 * STR;      // [64][STR]  TRANSPOSED: Kt[d][key]
    float* Vs = Kt + 64 * STR;      // [64][STR]  key-row major
    float* Ps = Vs + 64 * STR;      // [64][STR]  q-row major

    const int qt = blockIdx.x, h = blockIdx.y, b = blockIdx.z;
    const int tid = threadIdx.x;
    const int tx = tid & 15, ty = tid >> 4;
    const int q0 = qt * 64;

    // load Q tile: 64 rows x 64 cols = 1024 float4
    for (int i = tid; i < 64 * 16; i += 256) {
        int r = i >> 4, cg = (i & 15) << 2;
        float4 v = *(const float4*)(g_q + ((size_t)((b * SEQ + q0 + r) * H + h)) * D + cg);
        *(float4*)&Qs[r * STR + cg] = v;
    }

    float m[4], l[4], O[4][4];
#pragma unroll
    for (int i = 0; i < 4; i++) {
        m[i] = -1e30f; l[i] = 0.f;
#pragma unroll
        for (int j = 0; j < 4; j++) O[i][j] = 0.f;
    }

    for (int k0 = 0; k0 < SEQ; k0 += 64) {
        __syncthreads();  // prior-iter smem reads done
        // load K (transposed) and V tiles
        for (int i = tid; i < 64 * 16; i += 256) {
            int r = i >> 4, cg = (i & 15) << 2;
            size_t base = ((size_t)((b * SEQ + k0 + r) * H + h)) * D + cg;
            float4 kv = *(const float4*)(g_k + base);
            Kt[(cg + 0) * STR + r] = kv.x;
            Kt[(cg + 1) * STR + r] = kv.y;
            Kt[(cg + 2) * STR + r] = kv.z;
            Kt[(cg + 3) * STR + r] = kv.w;
            *(float4*)&Vs[r * STR + cg] = *(const float4*)(g_v + base);
        }
        __syncthreads();

        // GEMM1: s[i][j] = sum_d Q[4ty+i][d] * K[4tx+j][d]   (scale already in Q)
        float s[4][4] = {};
#pragma unroll
        for (int d = 0; d < 64; d += 4) {
            float4 qa[4], kb[4];
#pragma unroll
            for (int i = 0; i < 4; i++) qa[i] = *(const float4*)&Qs[(4 * ty + i) * STR + d];
#pragma unroll
            for (int dd = 0; dd < 4; dd++) kb[dd] = *(const float4*)&Kt[(d + dd) * STR + 4 * tx];
#pragma unroll
            for (int i = 0; i < 4; i++)
#pragma unroll
                for (int j = 0; j < 4; j++)
                    s[i][j] += f4c(qa[i], 0) * f4c(kb[0], j) + f4c(qa[i], 1) * f4c(kb[1], j)
                             + f4c(qa[i], 2) * f4c(kb[2], j) + f4c(qa[i], 3) * f4c(kb[3], j);
        }

        // online softmax update (row stats reduced over the 16-lane tx group)
        float p[4][4];
#pragma unroll
        for (int i = 0; i < 4; i++) {
            float tm = fmaxf(fmaxf(s[i][0], s[i][1]), fmaxf(s[i][2], s[i][3]));
#pragma unroll
            for (int msk = 1; msk < 16; msk <<= 1)
                tm = fmaxf(tm, __shfl_xor_sync(0xffffffffu, tm, msk));
            float mn = fmaxf(m[i], tm);
            float corr = __expf(m[i] - mn);
            m[i] = mn;
            float rs = 0.f;
#pragma unroll
            for (int j = 0; j < 4; j++) {
                p[i][j] = __expf(s[i][j] - mn);
                rs += p[i][j];
            }
#pragma unroll
            for (int msk = 1; msk < 16; msk <<= 1)
                rs += __shfl_xor_sync(0xffffffffu, rs, msk);
            l[i] = l[i] * corr + rs;
#pragma unroll
            for (int j = 0; j < 4; j++) O[i][j] *= corr;
        }

        // store P tile
#pragma unroll
        for (int i = 0; i < 4; i++) {
            float4 pv = {p[i][0], p[i][1], p[i][2], p[i][3]};
            *(float4*)&Ps[(4 * ty + i) * STR + 4 * tx] = pv;
        }
        __syncthreads();

        // GEMM2: O[i][j] += sum_jk P[4ty+i][jk] * V[jk][4tx+j]
#pragma unroll
        for (int jk = 0; jk < 64; jk += 4) {
            float4 pa[4], vb[4];
#pragma unroll
            for (int i = 0; i < 4; i++) pa[i] = *(const float4*)&Ps[(4 * ty + i) * STR + jk];
#pragma unroll
            for (int jj = 0; jj < 4; jj++) vb[jj] = *(const float4*)&Vs[(jk + jj) * STR + 4 * tx];
#pragma unroll
            for (int i = 0; i < 4; i++)
#pragma unroll
                for (int j = 0; j < 4; j++)
                    O[i][j] += f4c(pa[i], 0) * f4c(vb[0], j) + f4c(pa[i], 1) * f4c(vb[1], j)
                             + f4c(pa[i], 2) * f4c(vb[2], j) + f4c(pa[i], 3) * f4c(vb[3], j);
        }
    }

    // normalize + write: g_ao[tok, h*64 + c]
#pragma unroll
    for (int i = 0; i < 4; i++) {
        float inv = 1.0f / l[i];
        float4 o = {O[i][0] * inv, O[i][1] * inv, O[i][2] * inv, O[i][3] * inv};
        *(float4*)(g_ao + (size_t)(b * SEQ + q0 + 4 * ty + i) * HD + h * 64 + 4 * tx) = o;
    }
}

// ---------------- launch ----------------
extern "C" void kernel_launch(void* const* d_in, const int* in_sizes, int n_in,
                              void* d_out, int out_size) {
    const float* q         = (const float*)d_in[0];   // [4,2048,1024]
    const int*   q_coords  = (const int*)  d_in[1];   // [4,2048,2]
    const float* kv        = (const float*)d_in[2];   // [4,2048,1024]
    const int*   kv_coords = (const int*)  d_in[3];   // [4,2048,2]
    const float* Wq        = (const float*)d_in[4];   // [1024,16,64]
    const float* Wk        = (const float*)d_in[5];   // [1024,4,64]
    const float* Wv        = (const float*)d_in[6];   // [1024,4,64]
    const float* Wo        = (const float*)d_in[7];   // [256,1024]
    float* out = (float*)d_out;                       // [4,2048,1024]

    float *gq, *gk, *gv, *gao, *gwq;
    cudaGetSymbolAddress((void**)&gq,  g_q);
    cudaGetSymbolAddress((void**)&gk,  g_k);
    cudaGetSymbolAddress((void**)&gv,  g_v);
    cudaGetSymbolAddress((void**)&gao, g_ao);
    cudaGetSymbolAddress((void**)&gwq, g_Wqeff);

    // 1. group-sum Wq
    wqeff_kernel<<<(IND * HD + 255) / 256, 256>>>(Wq);

    // 2. projections
    dim3 gp(HD / 64, NTOK / 64);
    gemm_rrr<<<gp, 256>>>(q,  gwq, gq, NTOK, HD, IND);
    gemm_rrr<<<gp, 256>>>(kv, Wk,  gk, NTOK, HD, IND);
    gemm_rrr<<<gp, 256>>>(kv, Wv,  gv, NTOK, HD, IND);

    // 3. RoPE (+ fold 1/sqrt(64) into q)
    int rope_n = NTOK * H * 32;
    rope_kernel<<<(rope_n + 255) / 256, 256>>>(gq, q_coords, 0.125f);
    rope_kernel<<<(rope_n + 255) / 256, 256>>>(gk, kv_coords, 1.0f);

    // 4. flash attention
    static int attr_done = 0;
    size_t smem = (size_t)4 * 64 * STR * sizeof(float);   // ~68 KB
    cudaFuncSetAttribute(attn_kernel, cudaFuncAttributeMaxDynamicSharedMemorySize, (int)smem);
    (void)attr_done;
    dim3 ga(SEQ / 64, H, BATCH);
    attn_kernel<<<ga, 256, smem>>>();

    // 5. out projection
    dim3 go(IND / 64, NTOK / 64);
    gemm_rrr<<<go, 256>>>(gao, Wo, out, NTOK, IND, HD);
}

// round 2
// speedup vs baseline: 1.1062x; 1.1062x over previous
#include <cuda_runtime.h>
#include <math.h>

#define BATCH 4
#define SEQ 2048
#define IND 1024
#define H 4          // kv heads
#define D 64
#define HD 256       // H*D
#define NTOK (BATCH*SEQ)  // 8192

// ---------------- scratch (no allocs allowed) ----------------
__device__ __align__(16) float g_Wqeff[IND*HD];     // 1 MB
__device__ __align__(16) float g_q[NTOK*HD];        // 8 MB  (roped, pre-scaled by 1/8)
__device__ __align__(16) float g_k[NTOK*HD];        // 8 MB  (roped)
__device__ __align__(16) float g_v[NTOK*HD];        // 8 MB
__device__ __align__(16) float g_ao[NTOK*HD];       // 8 MB  (attention output, [tok, h*64+d])

// ---------------- Wq group-sum: Wq [1024,16,64] -> Wq_eff [1024, 4*64] ----------------
__global__ void wqeff_kernel(const float* __restrict__ Wq) {
    int idx = blockIdx.x * blockDim.x + threadIdx.x;
    if (idx >= IND * HD) return;
    int i  = idx / HD;
    int hd = idx % HD;
    int h = hd / D, d = hd % D;
    const float* base = Wq + (size_t)i * 1024 + (h * 4) * 64 + d;
    g_Wqeff[idx] = base[0] + base[64] + base[128] + base[192];
}

// ---------------- fp32 SGEMM: C[M,N] = A[M,K] @ B[K,N], row-major ----------------
// 128x128 tile, BK=8, 256 threads, 8x8 per thread, double-buffered smem.
__global__ __launch_bounds__(256, 2) void sgemm128(const float* __restrict__ A,
                                                   const float* __restrict__ Bm,
                                                   float* __restrict__ C,
                                                   int M, int N, int K) {
    __shared__ __align__(16) float As[2][8][132];   // transposed: As[b][k][m], pad 132
    __shared__ __align__(16) float Bs[2][8][128];
    const int tid = threadIdx.x;
    const int tx = tid & 15, ty = tid >> 4;
    const int m0 = blockIdx.y * 128, n0 = blockIdx.x * 128;

    const int arow = tid >> 1, acol = (tid & 1) << 2;       // A: 128 rows x 8 cols
    const int brow = tid >> 5, bcol = (tid & 31) << 2;      // B: 8 rows x 128 cols
    const float* Aptr = A + (size_t)(m0 + arow) * K + acol;
    const float* Bptr = Bm + (size_t)brow * N + n0 + bcol;

    // prologue: tile 0
    {
        float4 av = *(const float4*)Aptr;
        float4 bv = *(const float4*)Bptr;
        As[0][acol + 0][arow] = av.x;
        As[0][acol + 1][arow] = av.y;
        As[0][acol + 2][arow] = av.z;
        As[0][acol + 3][arow] = av.w;
        *(float4*)&Bs[0][brow][bcol] = bv;
    }
    __syncthreads();

    float acc[8][8] = {};
    int buf = 0;
    const int kIter = K >> 3;

    for (int t = 0; t < kIter; t++) {
        float4 av, bv;
        if (t + 1 < kIter) {
            av = *(const float4*)(Aptr + (size_t)(t + 1) * 8);
            bv = *(const float4*)(Bptr + (size_t)(t + 1) * 8 * N);
        }
#pragma unroll
        for (int k = 0; k < 8; k++) {
            float4 a0 = *(const float4*)&As[buf][k][4 * ty];
            float4 a1 = *(const float4*)&As[buf][k][4 * ty + 64];
            float4 b0 = *(const float4*)&Bs[buf][k][4 * tx];
            float4 b1 = *(const float4*)&Bs[buf][k][4 * tx + 64];
            float ar[8] = {a0.x, a0.y, a0.z, a0.w, a1.x, a1.y, a1.z, a1.w};
            float br[8] = {b0.x, b0.y, b0.z, b0.w, b1.x, b1.y, b1.z, b1.w};
#pragma unroll
            for (int i = 0; i < 8; i++)
#pragma unroll
                for (int j = 0; j < 8; j++)
                    acc[i][j] += ar[i] * br[j];
        }
        if (t + 1 < kIter) {
            buf ^= 1;
            As[buf][acol + 0][arow] = av.x;
            As[buf][acol + 1][arow] = av.y;
            As[buf][acol + 2][arow] = av.z;
            As[buf][acol + 3][arow] = av.w;
            *(float4*)&Bs[buf][brow][bcol] = bv;
            __syncthreads();
        }
    }

#pragma unroll
    for (int i = 0; i < 8; i++) {
        int row = m0 + 4 * ty + (i & 3) + ((i >> 2) << 6);
        float4 o0 = {acc[i][0], acc[i][1], acc[i][2], acc[i][3]};
        float4 o1 = {acc[i][4], acc[i][5], acc[i][6], acc[i][7]};
        *(float4*)(C + (size_t)row * N + n0 + 4 * tx)      = o0;
        *(float4*)(C + (size_t)row * N + n0 + 64 + 4 * tx) = o1;
    }
}

// ---------------- N-D RoPE (in place), coords int32 [ntok, 2], x [ntok, H, D] ----------------
__global__ void rope_kernel(float* __restrict__ x, const int* __restrict__ coords, float scale) {
    int idx = blockIdx.x * blockDim.x + threadIdx.x;
    if (idx >= NTOK * H * 32) return;
    int p   = idx & 31;
    int th  = idx >> 5;        // token*H + h
    int tok = th >> 2;
    int axis = p >> 4;
    int f    = p & 15;
    double inv = exp(-(double)f * (9.210340371976184 / 16.0)); // ln(10000)/16
    double ang = (double)coords[tok * 2 + axis] * inv;
    double sd, cd;
    sincos(ang, &sd, &cd);
    float sn = (float)sd, cs = (float)cd;
    float* px = x + (size_t)th * D + 2 * p;
    float x1 = px[0], x2 = px[1];
    px[0] = (x1 * cs - x2 * sn) * scale;
    px[1] = (x1 * sn + x2 * cs) * scale;
}

// ---------------- flash attention, fp32, BQ=128, BKV=128, 256 threads ----------------
// Swizzled transposed layout: element (d, r) of a [64 or 128]-row-major-by-d tile
// is stored at d*132 + (r ^ (((d>>2)&7)<<2)).  Reads of a 4-row group are one
// aligned float4 at d*132 + 4*((r4>>2) ^ ((d>>2)&7)).
__device__ __forceinline__ int sw_st(int d, int r) {
    return d * 132 + (r ^ (((d >> 2) & 7) << 2));
}
__device__ __forceinline__ const float4* sw_ld(const float* base, int d, int r4) {
    return (const float4*)(base + d * 132 + ((((r4 >> 2) ^ ((d >> 2) & 7))) << 2));
}

__global__ __launch_bounds__(256, 1) void attn_kernel() {
    extern __shared__ __align__(16) float sm[];
    float* Qt = sm;                 // [64][132]  Qt[d][r] swizzled
    float* Kt = Qt + 64 * 132;      // [64][132]  Kt[d][c] swizzled
    float* Pt = Kt + 64 * 132;      // [128][132] Pt[kv][r] swizzled
    float* Vs = Pt + 128 * 132;     // [128][68]  kv-row major

    const int qt = blockIdx.x, h = blockIdx.y, b = blockIdx.z;
    const int tid = threadIdx.x;
    const int tx = tid & 15, ty = tid >> 4;
    const int q0 = qt * 128;

    // load Q tile (128 tokens x 64 d) transposed+swizzled
    for (int i = tid; i < 128 * 16; i += 256) {
        int r = i >> 4, cg = (i & 15) << 2;
        float4 v = *(const float4*)(g_q + ((size_t)((b * SEQ + q0 + r) * H + h)) * D + cg);
        Qt[sw_st(cg + 0, r)] = v.x;
        Qt[sw_st(cg + 1, r)] = v.y;
        Qt[sw_st(cg + 2, r)] = v.z;
        Qt[sw_st(cg + 3, r)] = v.w;
    }

    float m[8], l[8], O[8][4];
#pragma unroll
    for (int i = 0; i < 8; i++) {
        m[i] = -1e30f; l[i] = 0.f;
#pragma unroll
        for (int j = 0; j < 4; j++) O[i][j] = 0.f;
    }

    for (int k0 = 0; k0 < SEQ; k0 += 128) {
        __syncthreads();   // protect Vs/Pt from overwrite while prev GEMM2 runs
        // load K (transpose+swizzle) and V tiles (128 tokens x 64 d)
        for (int i = tid; i < 128 * 16; i += 256) {
            int r = i >> 4, cg = (i & 15) << 2;
            size_t base = ((size_t)((b * SEQ + k0 + r) * H + h)) * D + cg;
            float4 kv4 = *(const float4*)(g_k + base);
            Kt[sw_st(cg + 0, r)] = kv4.x;
            Kt[sw_st(cg + 1, r)] = kv4.y;
            Kt[sw_st(cg + 2, r)] = kv4.z;
            Kt[sw_st(cg + 3, r)] = kv4.w;
            *(float4*)&Vs[r * 68 + cg] = *(const float4*)(g_v + base);
        }
        __syncthreads();

        // GEMM1: s[i][j] = sum_d Q[row(i)][d] * K[col(j)][d]  (scale folded into Q)
        float s[8][8] = {};
#pragma unroll 4
        for (int d = 0; d < 64; d++) {
            float4 a0 = *sw_ld(Qt, d, 4 * ty);
            float4 a1 = *sw_ld(Qt, d, 4 * ty + 64);
            float4 b0 = *sw_ld(Kt, d, 4 * tx);
            float4 b1 = *sw_ld(Kt, d, 4 * tx + 64);
            float ar[8] = {a0.x, a0.y, a0.z, a0.w, a1.x, a1.y, a1.z, a1.w};
            float br[8] = {b0.x, b0.y, b0.z, b0.w, b1.x, b1.y, b1.z, b1.w};
#pragma unroll
            for (int i = 0; i < 8; i++)
#pragma unroll
                for (int j = 0; j < 8; j++)
                    s[i][j] += ar[i] * br[j];
        }

        // online softmax (row stats over 16 tx lanes), write Pt
#pragma unroll
        for (int i = 0; i < 8; i++) {
            float tm = s[i][0];
#pragma unroll
            for (int j = 1; j < 8; j++) tm = fmaxf(tm, s[i][j]);
#pragma unroll
            for (int msk = 1; msk < 16; msk <<= 1)
                tm = fmaxf(tm, __shfl_xor_sync(0xffffffffu, tm, msk));
            float mn = fmaxf(m[i], tm);
            float corr = __expf(m[i] - mn);
            m[i] = mn;
            float rs = 0.f;
#pragma unroll
            for (int j = 0; j < 8; j++) {
                s[i][j] = __expf(s[i][j] - mn);
                rs += s[i][j];
            }
#pragma unroll
            for (int msk = 1; msk < 16; msk <<= 1)
                rs += __shfl_xor_sync(0xffffffffu, rs, msk);
            l[i] = l[i] * corr + rs;
#pragma unroll
            for (int j = 0; j < 4; j++) O[i][j] *= corr;
        }
        {
            int r_lo = 4 * ty, r_hi = 4 * ty + 64;
#pragma unroll
            for (int i = 0; i < 8; i++) {
                int r = (i < 4) ? (r_lo + i) : (r_hi + i - 4);
#pragma unroll
                for (int j = 0; j < 8; j++) {
                    int c = 4 * tx + (j & 3) + ((j >> 2) << 6);
                    Pt[sw_st(c, r)] = s[i][j];
                }
            }
        }
        __syncthreads();

        // GEMM2: O[i][jd] += sum_kv P[row(i)][kv] * V[kv][4tx+jd]
#pragma unroll 4
        for (int kv = 0; kv < 128; kv++) {
            float4 a0 = *sw_ld(Pt, kv, 4 * ty);
            float4 a1 = *sw_ld(Pt, kv, 4 * ty + 64);
            float4 b0 = *(const float4*)&Vs[kv * 68 + 4 * tx];
            float ar[8] = {a0.x, a0.y, a0.z, a0.w, a1.x, a1.y, a1.z, a1.w};
            float br[4] = {b0.x, b0.y, b0.z, b0.w};
#pragma unroll
            for (int i = 0; i < 8; i++)
#pragma unroll
                for (int j = 0; j < 4; j++)
                    O[i][j] += ar[i] * br[j];
        }
    }

    // normalize + write: g_ao[tok, h*64 + c]
#pragma unroll
    for (int i = 0; i < 8; i++) {
        int row = q0 + 4 * ty + (i & 3) + ((i >> 2) << 6);
        float inv = 1.0f / l[i];
        float4 o = {O[i][0] * inv, O[i][1] * inv, O[i][2] * inv, O[i][3] * inv};
        *(float4*)(g_ao + (size_t)(b * SEQ + row) * HD + h * 64 + 4 * tx) = o;
    }
}

// ---------------- launch ----------------
extern "C" void kernel_launch(void* const* d_in, const int* in_sizes, int n_in,
                              void* d_out, int out_size) {
    const float* q         = (const float*)d_in[0];   // [4,2048,1024]
    const int*   q_coords  = (const int*)  d_in[1];   // [4,2048,2]
    const float* kv        = (const float*)d_in[2];   // [4,2048,1024]
    const int*   kv_coords = (const int*)  d_in[3];   // [4,2048,2]
    const float* Wq        = (const float*)d_in[4];   // [1024,16,64]
    const float* Wk        = (const float*)d_in[5];   // [1024,4,64]
    const float* Wv        = (const float*)d_in[6];   // [1024,4,64]
    const float* Wo        = (const float*)d_in[7];   // [256,1024]
    float* out = (float*)d_out;                       // [4,2048,1024]

    float *gq, *gk, *gv, *gao, *gwq;
    cudaGetSymbolAddress((void**)&gq,  g_q);
    cudaGetSymbolAddress((void**)&gk,  g_k);
    cudaGetSymbolAddress((void**)&gv,  g_v);
    cudaGetSymbolAddress((void**)&gao, g_ao);
    cudaGetSymbolAddress((void**)&gwq, g_Wqeff);

    // 1. group-sum Wq
    wqeff_kernel<<<(IND * HD + 255) / 256, 256>>>(Wq);

    // 2. projections: M=8192, N=256, K=1024
    dim3 gp(HD / 128, NTOK / 128);
    sgemm128<<<gp, 256>>>(q,  gwq, gq, NTOK, HD, IND);
    sgemm128<<<gp, 256>>>(kv, Wk,  gk, NTOK, HD, IND);
    sgemm128<<<gp, 256>>>(kv, Wv,  gv, NTOK, HD, IND);

    // 3. RoPE (+ fold 1/sqrt(64) into q)
    int rope_n = NTOK * H * 32;
    rope_kernel<<<(rope_n + 255) / 256, 256>>>(gq, q_coords, 0.125f);
    rope_kernel<<<(rope_n + 255) / 256, 256>>>(gk, kv_coords, 1.0f);

    // 4. flash attention: grid (16, 4, 4)
    size_t smem = (size_t)(64 * 132 * 2 + 128 * 132 + 128 * 68) * sizeof(float); // ~166 KB
    cudaFuncSetAttribute(attn_kernel, cudaFuncAttributeMaxDynamicSharedMemorySize, (int)smem);
    dim3 ga(SEQ / 128, H, BATCH);
    attn_kernel<<<ga, 256, smem>>>();

    // 5. out projection: M=8192, N=1024, K=256
    dim3 go(IND / 128, NTOK / 128);
    sgemm128<<<go, 256>>>(gao, Wo, out, NTOK, IND, HD);
}